// round 11
// baseline (speedup 1.0000x reference)
#include <cuda_runtime.h>
#include <cstdint>

// out[b, p*64+m] = x[b,m]*(w[p,0]-w[p,1]) + S[b]*w[p,1],  S[b]=sum_n x[b,n]
// indices = 1 - eye(64) => closed form; indices input unused.
//
// Two-phase split to de-mix the DRAM stream:
//   Phase 1 (pure read):  S[b] = rowsum(x[b,:]); x loaded with evict_last
//                         policy so all 64MiB of x stays resident in L2.
//   Phase 2 (pure write): re-read x (L2 hits) + S (L2 hit), stream 512MiB
//                         of stores with .cs. DRAM sees ~pure write bursts.

#define MAX_ROWS 262144
__device__ float g_S[MAX_ROWS];   // 1MB scratch (allocation-free rule)

// ---------------- Phase 1: row sums, keep x hot in L2 ----------------
// Warp handles 2 rows: lanes 0..15 -> row 2q, lanes 16..31 -> row 2q+1.
__global__ void __launch_bounds__(256)
rowsum_kernel(const float4* __restrict__ x4, int npairs)
{
    int lane = threadIdx.x & 31;
    int half = lane >> 4;
    int sub  = lane & 15;
    int pair = (int)((blockIdx.x * blockDim.x + threadIdx.x) >> 5);
    if (pair >= npairs) return;

    size_t row = 2 * (size_t)pair + half;
    const float* p = (const float*)(x4 + row * 16 + sub);

    float4 v;
    asm volatile(
        "{\n\t"
        ".reg .b64 pol;\n\t"
        "createpolicy.fractional.L2::evict_last.b64 pol, 1.0;\n\t"
        "ld.global.nc.L2::cache_hint.v4.f32 {%0,%1,%2,%3}, [%4], pol;\n\t"
        "}"
        : "=f"(v.x), "=f"(v.y), "=f"(v.z), "=f"(v.w)
        : "l"(p));

    float s = (v.x + v.y) + (v.z + v.w);
    #pragma unroll
    for (int off = 8; off > 0; off >>= 1)
        s += __shfl_xor_sync(0xffffffffu, s, off);

    if (sub == 0) g_S[row] = s;
}

// ---------------- Phase 2: emit 512MiB, reads hit L2 -----------------
__global__ void __launch_bounds__(256, 6)
emit_kernel(const float4* __restrict__ x4,
            const float* __restrict__ w,
            float4* __restrict__ out4,
            int npairs)
{
    const float4* __restrict__ w4 = (const float4*)w;
    float wa[8], ws[8];
    #pragma unroll
    for (int i = 0; i < 4; i++) {
        float4 q = __ldg(&w4[i]);
        wa[2*i]     = q.x - q.y;  ws[2*i]     = q.y;
        wa[2*i + 1] = q.z - q.w;  ws[2*i + 1] = q.w;
    }

    int lane = threadIdx.x & 31;
    int half = lane >> 4;
    int sub  = lane & 15;

    int warpsTotal = (int)((gridDim.x * blockDim.x) >> 5);
    int warpId     = (int)((blockIdx.x * blockDim.x + threadIdx.x) >> 5);

    for (int pair = warpId; pair < npairs; pair += warpsTotal) {
        size_t row = 2 * (size_t)pair + half;

        float4 xv = __ldg(&x4[row * 16 + sub]);   // L2 hit (evict_last resident)
        float  S  = __ldg(&g_S[row]);             // L2/L1 hit, half-warp uniform

        float4* __restrict__ orow = out4 + row * 128;
        #pragma unroll
        for (int k = 0; k < 8; k++) {
            float sc = S * ws[k];
            float4 r;
            r.x = fmaf(xv.x, wa[k], sc);
            r.y = fmaf(xv.y, wa[k], sc);
            r.z = fmaf(xv.z, wa[k], sc);
            r.w = fmaf(xv.w, wa[k], sc);
            __stcs(&orow[sub + 16 * k], r);       // evict-first write stream
        }
    }
}

extern "C" void kernel_launch(void* const* d_in, const int* in_sizes, int n_in,
                              void* d_out, int out_size)
{
    const float* x = (const float*)d_in[0];   // (B, 64) fp32
    const float* w = (const float*)d_in[1];   // (8, 2) fp32
    // d_in[2] = indices (unused: 1 - eye closed form)

    int nrows  = in_sizes[0] / 64;            // B = 262144
    int npairs = nrows / 2;                   // 131072

    // Phase 1: one warp per pair, non-persistent.
    int blocks1 = (npairs * 32 + 255) / 256;  // 16384
    rowsum_kernel<<<blocks1, 256>>>((const float4*)x, npairs);

    // Phase 2: persistent, ~6 blocks/SM.
    emit_kernel<<<912, 256>>>((const float4*)x, w, (float4*)d_out, npairs);
}

// round 12
// speedup vs baseline: 1.0708x; 1.0708x over previous
#include <cuda_runtime.h>
#include <cstdint>

// out[b, p*64+m] = x[b,m]*(w[p,0]-w[p,1]) + S[b]*w[p,1],  S[b]=sum_n x[b,n]
// indices = 1 - eye(64) => closed form; indices input unused.
//
// 256-bit LDG/STG variant (sm_100+ v8.b32). Persistent warps, 2 rows per
// warp iteration: lanes 0..15 -> row 2q, lanes 16..31 -> row 2q+1.
// Lane loads one float8 chunk of its x row (chunk oct = lane&7; each 8-lane
// group covers the full 64-float row, so lanes 8..15 duplicate — L1
// broadcast). Row sum = 3-step butterfly within each 8-lane group.
// Stores: 4 x STG.256 per lane cover the 512-float output row.
//   k=0..3: slot j = (lane&15) + 16k -> p = 2k + ((lane>>3)&1), m-chunk = oct.
__global__ void __launch_bounds__(256, 6)
perm_v8_kernel(const float* __restrict__ x,
               const float* __restrict__ w,
               float* __restrict__ out,
               int npairs)
{
    // Preload all 16 weight floats (warp-uniform).
    const float4* __restrict__ w4 = (const float4*)w;
    float wa[8], ws[8];
    #pragma unroll
    for (int i = 0; i < 4; i++) {
        float4 q = __ldg(&w4[i]);
        wa[2*i]     = q.x - q.y;  ws[2*i]     = q.y;
        wa[2*i + 1] = q.z - q.w;  ws[2*i + 1] = q.w;
    }

    int lane = threadIdx.x & 31;
    int half = lane >> 4;          // row within the pair
    int sub  = lane & 15;          // float8 slot id base
    int oct  = lane & 7;           // x-chunk (8 floats) this lane owns
    int hi   = (lane >> 3) & 1;    // p parity selector

    int warpsTotal = (int)((gridDim.x * blockDim.x) >> 5);
    int warpId     = (int)((blockIdx.x * blockDim.x + threadIdx.x) >> 5);

    for (int pair = warpId; pair < npairs; pair += warpsTotal) {
        size_t row = 2 * (size_t)pair + half;

        // 256-bit load of 8 consecutive x elements: m = 8*oct .. 8*oct+7
        const float* xp = x + row * 64 + oct * 8;
        uint32_t u0,u1,u2,u3,u4,u5,u6,u7;
        asm volatile(
            "ld.global.nc.v8.b32 {%0,%1,%2,%3,%4,%5,%6,%7}, [%8];"
            : "=r"(u0),"=r"(u1),"=r"(u2),"=r"(u3),
              "=r"(u4),"=r"(u5),"=r"(u6),"=r"(u7)
            : "l"(xp));
        float v0 = __uint_as_float(u0), v1 = __uint_as_float(u1);
        float v2 = __uint_as_float(u2), v3 = __uint_as_float(u3);
        float v4 = __uint_as_float(u4), v5 = __uint_as_float(u5);
        float v6 = __uint_as_float(u6), v7 = __uint_as_float(u7);

        // Row sum: each 8-lane group covers the whole row; butterfly 4,2,1.
        float s = ((v0 + v1) + (v2 + v3)) + ((v4 + v5) + (v6 + v7));
        #pragma unroll
        for (int off = 4; off > 0; off >>= 1)
            s += __shfl_xor_sync(0xffffffffu, s, off);
        float S = s;

        float* __restrict__ orow = out + row * 512;
        #pragma unroll
        for (int k = 0; k < 4; k++) {
            // p = 2k + hi (compile-time pair of candidates, runtime select)
            float A  = hi ? wa[2*k + 1] : wa[2*k];
            float sc = S * (hi ? ws[2*k + 1] : ws[2*k]);
            uint32_t r0 = __float_as_uint(fmaf(v0, A, sc));
            uint32_t r1 = __float_as_uint(fmaf(v1, A, sc));
            uint32_t r2 = __float_as_uint(fmaf(v2, A, sc));
            uint32_t r3 = __float_as_uint(fmaf(v3, A, sc));
            uint32_t r4 = __float_as_uint(fmaf(v4, A, sc));
            uint32_t r5 = __float_as_uint(fmaf(v5, A, sc));
            uint32_t r6 = __float_as_uint(fmaf(v6, A, sc));
            uint32_t r7 = __float_as_uint(fmaf(v7, A, sc));
            // slot j = sub + 16k -> 8 floats at orow + 8j
            float* op = orow + (sub + 16 * k) * 8;
            asm volatile(
                "st.global.cs.v8.b32 [%0], {%1,%2,%3,%4,%5,%6,%7,%8};"
                :: "l"(op),
                   "r"(r0),"r"(r1),"r"(r2),"r"(r3),
                   "r"(r4),"r"(r5),"r"(r6),"r"(r7)
                : "memory");
        }
    }
}

extern "C" void kernel_launch(void* const* d_in, const int* in_sizes, int n_in,
                              void* d_out, int out_size)
{
    const float* x = (const float*)d_in[0];   // (B, 64) fp32
    const float* w = (const float*)d_in[1];   // (8, 2) fp32
    // d_in[2] = indices (unused: 1 - eye closed form)

    int nrows  = in_sizes[0] / 64;            // B = 262144
    int npairs = nrows / 2;                   // 131072

    int blocks = 912;                         // ~6 blocks/SM, grid-stride
    perm_v8_kernel<<<blocks, 256>>>(x, w, (float*)d_out, npairs);
}

// round 13
// speedup vs baseline: 1.0781x; 1.0068x over previous
#include <cuda_runtime.h>

// out[b, p*64+m] = x[b,m]*(w[p,0]-w[p,1]) + S[b]*w[p,1],  S[b]=sum_n x[b,n]
// indices = 1 - eye(64)  => closed form; indices input unused.
//
// Converged kernel (R6 structure). HBM-write-bound at the measured device
// ceiling (~5.7 TB/s effective for a 9:1 write:read fp32 stream); all other
// levers (MLP, TMA store, cache policy, stream de-mixing, 256-bit ops)
// verified neutral or worse.
//
// Persistent warps, 2 rows per warp iteration:
//   lanes 0..15  -> row 2*pair,   lanes 16..31 -> row 2*pair+1
//   lane's float4 covers elements m = 4*(lane&15) .. +3 of its row
//   butterfly over offsets 8,4,2,1 reduces each 16-lane group to its row sum
//   k-loop k=0..7: float4 slot (lane&15)+16k -> p=k uniform, same m block
__global__ void __launch_bounds__(256, 6)
perm_closed_kernel(const float4* __restrict__ x4,
                   const float* __restrict__ w,
                   float4* __restrict__ out4,
                   int npairs)
{
    // Preload all 16 weight floats once per warp lifetime (warp-uniform).
    const float4* __restrict__ w4 = (const float4*)w;
    float wa[8], ws[8];
    #pragma unroll
    for (int i = 0; i < 4; i++) {
        float4 q = __ldg(&w4[i]);
        wa[2*i]     = q.x - q.y;  ws[2*i]     = q.y;
        wa[2*i + 1] = q.z - q.w;  ws[2*i + 1] = q.w;
    }

    int lane = threadIdx.x & 31;
    int half = lane >> 4;        // which row of the pair
    int sub  = lane & 15;        // float4 slot within the row (16 per row)

    int warpsTotal = (int)((gridDim.x * blockDim.x) >> 5);
    int warpId     = (int)((blockIdx.x * blockDim.x + threadIdx.x) >> 5);

    // Per-lane base pointers; advance by constant stride each iteration.
    size_t row0   = 2 * (size_t)warpId + half;
    const float4* __restrict__ xp = x4  + row0 * 16  + sub;
    float4*       __restrict__ op = out4 + row0 * 128 + sub;
    const size_t xstep = 2 * (size_t)warpsTotal * 16;    // float4 units
    const size_t ostep = 2 * (size_t)warpsTotal * 128;

    for (int pair = warpId; pair < npairs;
         pair += warpsTotal, xp += xstep, op += ostep) {
        float4 xv = __ldcs(xp);

        // Row sum: 16 lanes per row; butterfly stays within each half-warp.
        float s = (xv.x + xv.y) + (xv.z + xv.w);
        #pragma unroll
        for (int off = 8; off > 0; off >>= 1)
            s += __shfl_xor_sync(0xffffffffu, s, off);
        float S = s;

        #pragma unroll
        for (int k = 0; k < 8; k++) {
            float sc = S * ws[k];
            float4 r;
            r.x = fmaf(xv.x, wa[k], sc);
            r.y = fmaf(xv.y, wa[k], sc);
            r.z = fmaf(xv.z, wa[k], sc);
            r.w = fmaf(xv.w, wa[k], sc);
            __stcs(op + 16 * k, r);     // evict-first streaming store
        }
    }
}

extern "C" void kernel_launch(void* const* d_in, const int* in_sizes, int n_in,
                              void* d_out, int out_size)
{
    const float* x = (const float*)d_in[0];   // (B, 64) fp32
    const float* w = (const float*)d_in[1];   // (8, 2) fp32
    // d_in[2] = indices (unused: 1 - eye closed form)

    int nrows  = in_sizes[0] / 64;            // B = 262144
    int npairs = nrows / 2;                   // 131072

    // 6 blocks/SM x 152 SMs = full single-wave residency; grid-stride loop.
    perm_closed_kernel<<<912, 256>>>(
        (const float4*)x, w, (float4*)d_out, npairs);
}